// round 5
// baseline (speedup 1.0000x reference)
#include <cuda_runtime.h>
#include <cstddef>

#define FDIM 64
#define EMAX 1600000
#define NPART 64

// ---------------- device scratch (no allocations allowed) ----------------
__device__ float g_bufA[(size_t)EMAX * FDIM];   // 409.6 MB
__device__ float g_bufB[(size_t)EMAX * FDIM];   // 409.6 MB
__device__ float g_part[NPART * 2 * FDIM];      // partial stats buckets
__device__ __align__(16) float g_sums[2 * FDIM];
__device__ __align__(16) float g_scale[FDIM];   // gamma * rstd
__device__ __align__(16) float g_shift[FDIM];   // beta - mu * gamma * rstd

// softplus(x) = max(x,0) + log1p(exp(-|x|)); __logf(1+e) abs err < 6e-8.
__device__ __forceinline__ float softplusf(float x) {
    float e = __expf(-fabsf(x));
    return fmaxf(x, 0.0f) + __logf(1.0f + e);
}

__device__ __forceinline__ unsigned tf32_hi(float x) {
    unsigned r; asm("cvt.rna.tf32.f32 %0, %1;" : "=r"(r) : "f"(x)); return r;
}

__device__ __forceinline__ void mma_tf32(float* c, const unsigned* a,
                                         unsigned b0, unsigned b1) {
    asm volatile(
        "mma.sync.aligned.m16n8k8.row.col.f32.tf32.tf32.f32 "
        "{%0,%1,%2,%3}, {%4,%5,%6,%7}, {%8,%9}, {%0,%1,%2,%3};"
        : "+f"(c[0]), "+f"(c[1]), "+f"(c[2]), "+f"(c[3])
        : "r"(a[0]), "r"(a[1]), "r"(a[2]), "r"(a[3]), "r"(b0), "r"(b1));
}

// ---------------- init: zero output + partial stats ----------------
__global__ void init_kernel(float* __restrict__ out, int n) {
    int i = blockIdx.x * blockDim.x + threadIdx.x;
    if (i < n) out[i] = 0.0f;
    if (i < NPART * 2 * FDIM) g_part[i] = 0.0f;
}

// ---------------- fused GEMM (tf32 mma, 3xTF32): out = act(in)@W + b; col stats ----
// CTA: 256 thr = 8 warps, tile 128 rows x 64 cols, K=64.
// Warp wb owns rows 16wb..16wb+15. m16n8k8 frags, frag-major smem (conflict-free).
// Raw fp32 staged in smem (fits 48KB static); tf32 hi/lo split done in mainloop.
template<bool ACT>
__device__ __forceinline__ void gemm_body(
    const float* __restrict__ in, float* __restrict__ out,
    const float* __restrict__ W, const float* __restrict__ bias)
{
    __shared__ float4 sA[2048];   // 32 KB: [s][wb][l] raw A frag (a0,a1,a2,a3)
    __shared__ float2 sW[2048];   // 16 KB: [s][j][l]  raw W frag (w0,w1)

    const int t  = threadIdx.x;
    const int wb = t >> 5;          // warp 0..7
    const int l  = t & 31;
    const int lq = l & 3;           // threadID_in_group (k / col selector)
    const int lg = l >> 2;          // groupID (row / n selector)

    // W frags: thread covers j = wb, its lane slot, all 8 k-steps.
    {
        const int n = wb * 8 + lg;
        #pragma unroll
        for (int s = 0; s < 8; s++) {
            int k0 = s * 8 + lq;
            sW[(s * 8 + wb) * 32 + l] = make_float2(W[k0 * 64 + n],
                                                    W[(k0 + 4) * 64 + n]);
        }
    }

    // A frags straight from gmem: rows r0 = 16wb+lg, r1 = r0+8; k = 8s+lq, +4.
    const size_t rowBase = (size_t)blockIdx.x * 128;
    const float* inB = in + rowBase * FDIM;
    const int r0 = wb * 16 + lg;
    const int r1 = r0 + 8;
    {
        #pragma unroll
        for (int s = 0; s < 8; s++) {
            int kA = s * 8 + lq, kB = kA + 4;
            float a0 = inB[(size_t)r0 * FDIM + kA];
            float a1 = inB[(size_t)r1 * FDIM + kA];
            float a2 = inB[(size_t)r0 * FDIM + kB];
            float a3 = inB[(size_t)r1 * FDIM + kB];
            if (ACT) {
                float scA = g_scale[kA], shA = g_shift[kA];
                float scB = g_scale[kB], shB = g_shift[kB];
                a0 = softplusf(fmaf(a0, scA, shA));
                a1 = softplusf(fmaf(a1, scA, shA));
                a2 = softplusf(fmaf(a2, scB, shB));
                a3 = softplusf(fmaf(a3, scB, shB));
            }
            sA[(s * 8 + wb) * 32 + l] = make_float4(a0, a1, a2, a3);
        }
    }
    __syncthreads();

    // ---- mainloop: 8 k-steps x 8 n-tiles x 3 mma (hi*hi + lo*hi + hi*lo) ----
    float acc[8][4];
    #pragma unroll
    for (int j = 0; j < 8; j++)
        #pragma unroll
        for (int c = 0; c < 4; c++) acc[j][c] = 0.0f;

    #pragma unroll
    for (int s = 0; s < 8; s++) {
        float4 a4 = sA[(s * 8 + wb) * 32 + l];
        unsigned ah[4], al[4];
        ah[0] = tf32_hi(a4.x); al[0] = __float_as_uint(a4.x - __uint_as_float(ah[0]));
        ah[1] = tf32_hi(a4.y); al[1] = __float_as_uint(a4.y - __uint_as_float(ah[1]));
        ah[2] = tf32_hi(a4.z); al[2] = __float_as_uint(a4.z - __uint_as_float(ah[2]));
        ah[3] = tf32_hi(a4.w); al[3] = __float_as_uint(a4.w - __uint_as_float(ah[3]));
        #pragma unroll
        for (int j = 0; j < 8; j++) {
            float2 w2 = sW[(s * 8 + j) * 32 + l];
            unsigned bh0 = tf32_hi(w2.x);
            unsigned bh1 = tf32_hi(w2.y);
            unsigned bl0 = __float_as_uint(w2.x - __uint_as_float(bh0));
            unsigned bl1 = __float_as_uint(w2.y - __uint_as_float(bh1));
            mma_tf32(acc[j], ah, bh0, bh1);
            mma_tf32(acc[j], al, bh0, bh1);
            mma_tf32(acc[j], ah, bl0, bl1);
        }
    }

    // ---- epilogue: +bias, store, column stats ----
    __syncthreads();                        // all sA/sW reads done; reuse sA
    float* sStats = reinterpret_cast<float*>(sA);
    if (t < 128) sStats[t] = 0.0f;

    float st1[16], st2[16];
    #pragma unroll
    for (int i = 0; i < 16; i++) { st1[i] = 0.0f; st2[i] = 0.0f; }

    float* outB = out + rowBase * FDIM;
    #pragma unroll
    for (int j = 0; j < 8; j++) {
        int c0 = j * 8 + lq * 2;
        float2 b2 = *reinterpret_cast<const float2*>(bias + c0);
        float y00 = acc[j][0] + b2.x, y01 = acc[j][1] + b2.y;
        float y10 = acc[j][2] + b2.x, y11 = acc[j][3] + b2.y;
        st1[j * 2]     += y00 + y10;
        st1[j * 2 + 1] += y01 + y11;
        st2[j * 2]     = fmaf(y00, y00, fmaf(y10, y10, st2[j * 2]));
        st2[j * 2 + 1] = fmaf(y01, y01, fmaf(y11, y11, st2[j * 2 + 1]));
        *reinterpret_cast<float2*>(outB + (size_t)r0 * FDIM + c0) = make_float2(y00, y01);
        *reinterpret_cast<float2*>(outB + (size_t)r1 * FDIM + c0) = make_float2(y10, y11);
    }
    // reduce over the 8 lanes sharing lq (xor 4, 8, 16)
    #pragma unroll
    for (int d = 4; d <= 16; d <<= 1) {
        #pragma unroll
        for (int i = 0; i < 16; i++) {
            st1[i] += __shfl_xor_sync(0xffffffffu, st1[i], d);
            st2[i] += __shfl_xor_sync(0xffffffffu, st2[i], d);
        }
    }
    __syncthreads();                        // sStats zeroed before atomics
    if (lg == 0) {   // lanes 0..3 hold column sums
        #pragma unroll
        for (int j = 0; j < 8; j++) {
            int c0 = j * 8 + lq * 2;
            atomicAdd(&sStats[c0],          st1[j * 2]);
            atomicAdd(&sStats[c0 + 1],      st1[j * 2 + 1]);
            atomicAdd(&sStats[64 + c0],     st2[j * 2]);
            atomicAdd(&sStats[64 + c0 + 1], st2[j * 2 + 1]);
        }
    }
    __syncthreads();
    if (t < 128)
        atomicAdd(&g_part[(blockIdx.x & (NPART - 1)) * 128 + t], sStats[t]);
}

__global__ void __launch_bounds__(256, 2)
gemm0_kernel(const float* __restrict__ in, const float* __restrict__ W,
             const float* __restrict__ bias) {
    gemm_body<false>(in, g_bufA, W, bias);
}
__global__ void __launch_bounds__(256, 2)
gemm1_kernel(const float* __restrict__ W, const float* __restrict__ bias) {
    gemm_body<true>(g_bufA, g_bufB, W, bias);
}
__global__ void __launch_bounds__(256, 2)
gemm2_kernel(const float* __restrict__ W, const float* __restrict__ bias) {
    gemm_body<true>(g_bufB, g_bufA, W, bias);
}

// ---------------- finalize: reduce partials -> scale/shift; re-zero partials ----
__global__ void finalize_kernel(const float* __restrict__ gamma,
                                const float* __restrict__ beta, float invE) {
    int t = threadIdx.x;   // 128 threads
    float tot = 0.0f;
    #pragma unroll 8
    for (int p = 0; p < NPART; p++) {
        tot += g_part[p * 128 + t];
        g_part[p * 128 + t] = 0.0f;
    }
    g_sums[t] = tot;
    __syncthreads();
    if (t < 64) {
        float mu  = g_sums[t] * invE;
        float var = fmaxf(g_sums[64 + t] * invE - mu * mu, 0.0f);
        float rstd = rsqrtf(var + 1e-5f);
        float sc = gamma[t] * rstd;
        g_scale[t] = sc;
        g_shift[t] = fmaf(-mu, sc, beta[t]);
    }
}

// ---------------- final: BN+softplus, dot w_out, edge dir, scatter-add ----------------
__global__ void __launch_bounds__(256)
force_kernel(const float* __restrict__ w_out, const float* __restrict__ b_out,
             const float* __restrict__ pos, const float* __restrict__ nbr,
             const int* __restrict__ eidx, float* __restrict__ out, int E)
{
    __shared__ float sw[FDIM], sc[FDIM], sh[FDIM];
    int t = threadIdx.x;
    if (t < FDIM) { sw[t] = w_out[t]; sc[t] = g_scale[t]; sh[t] = g_shift[t]; }
    __syncthreads();
    int e = blockIdx.x * blockDim.x + t;
    if (e >= E) return;

    const float4* hp = reinterpret_cast<const float4*>(g_bufA + (size_t)e * FDIM);
    float s = 0.0f;
    #pragma unroll
    for (int i = 0; i < 16; i++) {
        float4 v = hp[i];
        int c = i * 4;
        s += softplusf(fmaf(v.x, sc[c + 0], sh[c + 0])) * sw[c + 0];
        s += softplusf(fmaf(v.y, sc[c + 1], sh[c + 1])) * sw[c + 1];
        s += softplusf(fmaf(v.z, sc[c + 2], sh[c + 2])) * sw[c + 2];
        s += softplusf(fmaf(v.w, sc[c + 3], sh[c + 3])) * sw[c + 3];
    }
    s += b_out[0];

    int jn  = eidx[e];          // source j
    int in_ = eidx[E + e];      // target i
    float dx = pos[in_ * 3 + 0] + nbr[(size_t)e * 3 + 0] - pos[jn * 3 + 0];
    float dy = pos[in_ * 3 + 1] + nbr[(size_t)e * 3 + 1] - pos[jn * 3 + 1];
    float dz = pos[in_ * 3 + 2] + nbr[(size_t)e * 3 + 2] - pos[jn * 3 + 2];
    float inv = rsqrtf(fmaf(dx, dx, fmaf(dy, dy, dz * dz)));
    float f = s * inv;
    atomicAdd(out + in_ * 3 + 0, f * dx);
    atomicAdd(out + in_ * 3 + 1, f * dy);
    atomicAdd(out + in_ * 3 + 2, f * dz);
}

// ---------------- launch ----------------
extern "C" void kernel_launch(void* const* d_in, const int* in_sizes, int n_in,
                              void* d_out, int out_size)
{
    const float* edge_attr = (const float*)d_in[0];
    const float* nbr_shift = (const float*)d_in[1];
    const float* pos       = (const float*)d_in[2];
    const float* Ws        = (const float*)d_in[3];   // [3][64][64]
    const float* bs        = (const float*)d_in[4];   // [3][64]
    const float* gammas    = (const float*)d_in[5];   // [3][64]
    const float* betas     = (const float*)d_in[6];   // [3][64]
    const float* w_out     = (const float*)d_in[7];   // [64]
    const float* b_out     = (const float*)d_in[8];   // [1]
    const int*   eidx      = (const int*)d_in[9];     // [2][E] int32
    float* out = (float*)d_out;

    int E = in_sizes[0] / FDIM;     // 1,600,000
    if (E <= 0) return;
    float invE = 1.0f / (float)E;
    int gBlocks = E / 128;          // 12500

    init_kernel<<<(out_size + 255) / 256, 256>>>(out, out_size);

    gemm0_kernel<<<gBlocks, 256>>>(edge_attr, Ws, bs);
    finalize_kernel<<<1, 128>>>(gammas, betas, invE);

    gemm1_kernel<<<gBlocks, 256>>>(Ws + FDIM * FDIM, bs + FDIM);
    finalize_kernel<<<1, 128>>>(gammas + FDIM, betas + FDIM, invE);

    gemm2_kernel<<<gBlocks, 256>>>(Ws + 2 * FDIM * FDIM, bs + 2 * FDIM);
    finalize_kernel<<<1, 128>>>(gammas + 2 * FDIM, betas + 2 * FDIM, invE);

    force_kernel<<<(E + 255) / 256, 256>>>(w_out, b_out, pos, nbr_shift, eidx, out, E);
}

// round 7
// speedup vs baseline: 1.3531x; 1.3531x over previous
#include <cuda_runtime.h>
#include <cuda_bf16.h>
#include <cstdint>
#include <cstddef>

#define FDIM 64
#define EMAX 1600000
#define NPART 64

// ---------------- device scratch (no allocations allowed) ----------------
__device__ float g_bufA[(size_t)EMAX * FDIM];   // 409.6 MB
__device__ float g_bufB[(size_t)EMAX * FDIM];   // 409.6 MB
__device__ float g_part[NPART * 2 * FDIM];      // partial stats buckets
__device__ __align__(16) float g_sums[2 * FDIM];
__device__ __align__(16) float g_scale[FDIM];   // gamma * rstd
__device__ __align__(16) float g_shift[FDIM];   // beta - mu * gamma * rstd

// softplus(x) = max(x,0) + log1p(exp(-|x|)); __logf(1+e) abs err < 6e-8.
__device__ __forceinline__ float softplusf(float x) {
    float e = __expf(-fabsf(x));
    return fmaxf(x, 0.0f) + __logf(1.0f + e);
}

// split (x,y) into bf16 hi pack + bf16 residual pack (x in low half)
__device__ __forceinline__ void split2(float x, float y, uint32_t& hi, uint32_t& lo) {
    __nv_bfloat16 hx = __float2bfloat16_rn(x);
    __nv_bfloat16 hy = __float2bfloat16_rn(y);
    float rx = x - __bfloat162float(hx);
    float ry = y - __bfloat162float(hy);
    __nv_bfloat162 h; h.x = hx; h.y = hy;
    __nv_bfloat162 r = __floats2bfloat162_rn(rx, ry);
    hi = *reinterpret_cast<uint32_t*>(&h);
    lo = *reinterpret_cast<uint32_t*>(&r);
}

__device__ __forceinline__ void mma_bf16(float* c, uint32_t a0, uint32_t a1,
                                         uint32_t a2, uint32_t a3,
                                         uint32_t b0, uint32_t b1) {
    asm volatile(
        "mma.sync.aligned.m16n8k16.row.col.f32.bf16.bf16.f32 "
        "{%0,%1,%2,%3}, {%4,%5,%6,%7}, {%8,%9}, {%0,%1,%2,%3};"
        : "+f"(c[0]), "+f"(c[1]), "+f"(c[2]), "+f"(c[3])
        : "r"(a0), "r"(a1), "r"(a2), "r"(a3), "r"(b0), "r"(b1));
}

// ---------------- init: zero output + partial stats ----------------
__global__ void init_kernel(float* __restrict__ out, int n) {
    int i = blockIdx.x * blockDim.x + threadIdx.x;
    if (i < n) out[i] = 0.0f;
    if (i < NPART * 2 * FDIM) g_part[i] = 0.0f;
}

// ---------------- fused GEMM (bf16x2-split mma.sync.m16n8k16) ----------------
// CTA: 256 thr = 8 warps, tile 128 rows x 64 cols, K=64.
// Warp wb owns rows 16wb..16wb+15. Pre-split bf16 hi/lo staged frag-major in smem.
// Mainloop: 4 k-steps x 8 n-tiles x 3 HMMA (ah*bh + al*bh + ah*bl).
template<bool ACT>
__device__ __forceinline__ void gemm_body(
    const float* __restrict__ in, float* __restrict__ out,
    const float* __restrict__ W, const float* __restrict__ bias)
{
    __shared__ uint4 sAh[1024];   // 16 KB: [s(4)][wb(8)][l(32)] = a0h,a1h,a2h,a3h
    __shared__ uint4 sAl[1024];   // 16 KB: residuals
    __shared__ uint4 sW[1024];    // 16 KB: [s][j][l] = bh0,bh1,bl0,bl1   (48 KB total)

    const int t  = threadIdx.x;
    const int wb = t >> 5;          // warp 0..7
    const int l  = t & 31;
    const int lq = l & 3;           // threadID_in_group
    const int lg = l >> 2;          // groupID

    const size_t rowBase = (size_t)blockIdx.x * 128;
    const float* inB = in + rowBase * FDIM;
    const int r0 = wb * 16 + lg;
    const int r1 = r0 + 8;

    // W frags: thread covers n-tile j = wb, its lane slot, all 4 k-steps.
    {
        const int n = wb * 8 + lg;
        #pragma unroll
        for (int s = 0; s < 4; s++) {
            int k0 = 16 * s + 2 * lq;
            float w00 = W[k0 * 64 + n],       w01 = W[(k0 + 1) * 64 + n];
            float w10 = W[(k0 + 8) * 64 + n], w11 = W[(k0 + 9) * 64 + n];
            uint32_t bh0, bl0, bh1, bl1;
            split2(w00, w01, bh0, bl0);
            split2(w10, w11, bh1, bl1);
            sW[(s * 8 + wb) * 32 + l] = make_uint4(bh0, bh1, bl0, bl1);
        }
    }

    // A frags straight from gmem (float2 pairs), transform-on-load, split, stage.
    #pragma unroll
    for (int s = 0; s < 4; s++) {
        int k0 = 16 * s + 2 * lq;
        float2 v00 = *reinterpret_cast<const float2*>(inB + (size_t)r0 * FDIM + k0);
        float2 v20 = *reinterpret_cast<const float2*>(inB + (size_t)r0 * FDIM + k0 + 8);
        float2 v10 = *reinterpret_cast<const float2*>(inB + (size_t)r1 * FDIM + k0);
        float2 v30 = *reinterpret_cast<const float2*>(inB + (size_t)r1 * FDIM + k0 + 8);
        if (ACT) {
            float sc0 = g_scale[k0],     sh0 = g_shift[k0];
            float sc1 = g_scale[k0 + 1], sh1 = g_shift[k0 + 1];
            float sc8 = g_scale[k0 + 8], sh8 = g_shift[k0 + 8];
            float sc9 = g_scale[k0 + 9], sh9 = g_shift[k0 + 9];
            v00.x = softplusf(fmaf(v00.x, sc0, sh0)); v00.y = softplusf(fmaf(v00.y, sc1, sh1));
            v10.x = softplusf(fmaf(v10.x, sc0, sh0)); v10.y = softplusf(fmaf(v10.y, sc1, sh1));
            v20.x = softplusf(fmaf(v20.x, sc8, sh8)); v20.y = softplusf(fmaf(v20.y, sc9, sh9));
            v30.x = softplusf(fmaf(v30.x, sc8, sh8)); v30.y = softplusf(fmaf(v30.y, sc9, sh9));
        }
        uint32_t a0h, a0l, a1h, a1l, a2h, a2l, a3h, a3l;
        split2(v00.x, v00.y, a0h, a0l);   // a0 = row lg,   k 2lq..2lq+1
        split2(v10.x, v10.y, a1h, a1l);   // a1 = row lg+8
        split2(v20.x, v20.y, a2h, a2l);   // a2 = row lg,   k+8
        split2(v30.x, v30.y, a3h, a3l);   // a3 = row lg+8, k+8
        sAh[(s * 8 + wb) * 32 + l] = make_uint4(a0h, a1h, a2h, a3h);
        sAl[(s * 8 + wb) * 32 + l] = make_uint4(a0l, a1l, a2l, a3l);
    }
    __syncthreads();

    // ---- mainloop ----
    float acc[8][4];
    #pragma unroll
    for (int j = 0; j < 8; j++)
        #pragma unroll
        for (int c = 0; c < 4; c++) acc[j][c] = 0.0f;

    #pragma unroll
    for (int s = 0; s < 4; s++) {
        uint4 ah = sAh[(s * 8 + wb) * 32 + l];
        uint4 al = sAl[(s * 8 + wb) * 32 + l];
        #pragma unroll
        for (int j = 0; j < 8; j++) {
            uint4 w = sW[(s * 8 + j) * 32 + l];
            mma_bf16(acc[j], ah.x, ah.y, ah.z, ah.w, w.x, w.y);
            mma_bf16(acc[j], al.x, al.y, al.z, al.w, w.x, w.y);
            mma_bf16(acc[j], ah.x, ah.y, ah.z, ah.w, w.z, w.w);
        }
    }

    // ---- epilogue: +bias, store, column stats (layout identical to R5, proven) ----
    __syncthreads();                        // all smem reads done; reuse sAh
    float* sStats = reinterpret_cast<float*>(sAh);
    if (t < 128) sStats[t] = 0.0f;

    float st1[16], st2[16];
    #pragma unroll
    for (int i = 0; i < 16; i++) { st1[i] = 0.0f; st2[i] = 0.0f; }

    float* outB = out + rowBase * FDIM;
    #pragma unroll
    for (int j = 0; j < 8; j++) {
        int c0 = j * 8 + lq * 2;
        float2 b2 = *reinterpret_cast<const float2*>(bias + c0);
        float y00 = acc[j][0] + b2.x, y01 = acc[j][1] + b2.y;   // row r0
        float y10 = acc[j][2] + b2.x, y11 = acc[j][3] + b2.y;   // row r1
        st1[j * 2]     += y00 + y10;
        st1[j * 2 + 1] += y01 + y11;
        st2[j * 2]     = fmaf(y00, y00, fmaf(y10, y10, st2[j * 2]));
        st2[j * 2 + 1] = fmaf(y01, y01, fmaf(y11, y11, st2[j * 2 + 1]));
        *reinterpret_cast<float2*>(outB + (size_t)r0 * FDIM + c0) = make_float2(y00, y01);
        *reinterpret_cast<float2*>(outB + (size_t)r1 * FDIM + c0) = make_float2(y10, y11);
    }
    // reduce over the 8 lanes sharing lq (xor 4, 8, 16)
    #pragma unroll
    for (int d = 4; d <= 16; d <<= 1) {
        #pragma unroll
        for (int i = 0; i < 16; i++) {
            st1[i] += __shfl_xor_sync(0xffffffffu, st1[i], d);
            st2[i] += __shfl_xor_sync(0xffffffffu, st2[i], d);
        }
    }
    __syncthreads();                        // sStats zeroed before atomics
    if (lg == 0) {   // lanes 0..3 hold column sums
        #pragma unroll
        for (int j = 0; j < 8; j++) {
            int c0 = j * 8 + lq * 2;
            atomicAdd(&sStats[c0],          st1[j * 2]);
            atomicAdd(&sStats[c0 + 1],      st1[j * 2 + 1]);
            atomicAdd(&sStats[64 + c0],     st2[j * 2]);
            atomicAdd(&sStats[64 + c0 + 1], st2[j * 2 + 1]);
        }
    }
    __syncthreads();
    if (t < 128)
        atomicAdd(&g_part[(blockIdx.x & (NPART - 1)) * 128 + t], sStats[t]);
}

__global__ void __launch_bounds__(256)
gemm0_kernel(const float* __restrict__ in, const float* __restrict__ W,
             const float* __restrict__ bias) {
    gemm_body<false>(in, g_bufA, W, bias);
}
__global__ void __launch_bounds__(256)
gemm1_kernel(const float* __restrict__ W, const float* __restrict__ bias) {
    gemm_body<true>(g_bufA, g_bufB, W, bias);
}
__global__ void __launch_bounds__(256)
gemm2_kernel(const float* __restrict__ W, const float* __restrict__ bias) {
    gemm_body<true>(g_bufB, g_bufA, W, bias);
}

// ---------------- finalize: reduce partials -> scale/shift; re-zero partials ----
__global__ void finalize_kernel(const float* __restrict__ gamma,
                                const float* __restrict__ beta, float invE) {
    int t = threadIdx.x;   // 128 threads
    float tot = 0.0f;
    #pragma unroll 8
    for (int p = 0; p < NPART; p++) {
        tot += g_part[p * 128 + t];
        g_part[p * 128 + t] = 0.0f;
    }
    g_sums[t] = tot;
    __syncthreads();
    if (t < 64) {
        float mu  = g_sums[t] * invE;
        float var = fmaxf(g_sums[64 + t] * invE - mu * mu, 0.0f);
        float rstd = rsqrtf(var + 1e-5f);
        float sc = gamma[t] * rstd;
        g_scale[t] = sc;
        g_shift[t] = fmaf(-mu, sc, beta[t]);
    }
}

// ---------------- final: BN+softplus, dot w_out, edge dir, scatter-add ----------------
__global__ void __launch_bounds__(256)
force_kernel(const float* __restrict__ w_out, const float* __restrict__ b_out,
             const float* __restrict__ pos, const float* __restrict__ nbr,
             const int* __restrict__ eidx, float* __restrict__ out, int E)
{
    __shared__ float sw[FDIM], sc[FDIM], sh[FDIM];
    int t = threadIdx.x;
    if (t < FDIM) { sw[t] = w_out[t]; sc[t] = g_scale[t]; sh[t] = g_shift[t]; }
    __syncthreads();
    int e = blockIdx.x * blockDim.x + t;
    if (e >= E) return;

    const float4* hp = reinterpret_cast<const float4*>(g_bufA + (size_t)e * FDIM);
    float s = 0.0f;
    #pragma unroll
    for (int i = 0; i < 16; i++) {
        float4 v = hp[i];
        int c = i * 4;
        s += softplusf(fmaf(v.x, sc[c + 0], sh[c + 0])) * sw[c + 0];
        s += softplusf(fmaf(v.y, sc[c + 1], sh[c + 1])) * sw[c + 1];
        s += softplusf(fmaf(v.z, sc[c + 2], sh[c + 2])) * sw[c + 2];
        s += softplusf(fmaf(v.w, sc[c + 3], sh[c + 3])) * sw[c + 3];
    }
    s += b_out[0];

    int jn  = eidx[e];          // source j
    int in_ = eidx[E + e];      // target i
    float dx = pos[in_ * 3 + 0] + nbr[(size_t)e * 3 + 0] - pos[jn * 3 + 0];
    float dy = pos[in_ * 3 + 1] + nbr[(size_t)e * 3 + 1] - pos[jn * 3 + 1];
    float dz = pos[in_ * 3 + 2] + nbr[(size_t)e * 3 + 2] - pos[jn * 3 + 2];
    float inv = rsqrtf(fmaf(dx, dx, fmaf(dy, dy, dz * dz)));
    float f = s * inv;
    atomicAdd(out + in_ * 3 + 0, f * dx);
    atomicAdd(out + in_ * 3 + 1, f * dy);
    atomicAdd(out + in_ * 3 + 2, f * dz);
}

// ---------------- launch ----------------
extern "C" void kernel_launch(void* const* d_in, const int* in_sizes, int n_in,
                              void* d_out, int out_size)
{
    const float* edge_attr = (const float*)d_in[0];
    const float* nbr_shift = (const float*)d_in[1];
    const float* pos       = (const float*)d_in[2];
    const float* Ws        = (const float*)d_in[3];   // [3][64][64]
    const float* bs        = (const float*)d_in[4];   // [3][64]
    const float* gammas    = (const float*)d_in[5];   // [3][64]
    const float* betas     = (const float*)d_in[6];   // [3][64]
    const float* w_out     = (const float*)d_in[7];   // [64]
    const float* b_out     = (const float*)d_in[8];   // [1]
    const int*   eidx      = (const int*)d_in[9];     // [2][E] int32
    float* out = (float*)d_out;

    int E = in_sizes[0] / FDIM;     // 1,600,000
    if (E <= 0) return;
    float invE = 1.0f / (float)E;
    int gBlocks = E / 128;          // 12500

    init_kernel<<<(out_size + 255) / 256, 256>>>(out, out_size);

    gemm0_kernel<<<gBlocks, 256>>>(edge_attr, Ws, bs);
    finalize_kernel<<<1, 128>>>(gammas, betas, invE);

    gemm1_kernel<<<gBlocks, 256>>>(Ws + FDIM * FDIM, bs + FDIM);
    finalize_kernel<<<1, 128>>>(gammas + FDIM, betas + FDIM, invE);

    gemm2_kernel<<<gBlocks, 256>>>(Ws + 2 * FDIM * FDIM, bs + 2 * FDIM);
    finalize_kernel<<<1, 128>>>(gammas + 2 * FDIM, betas + 2 * FDIM, invE);

    force_kernel<<<(E + 255) / 256, 256>>>(w_out, b_out, pos, nbr_shift, eidx, out, E);
}